// round 6
// baseline (speedup 1.0000x reference)
#include <cuda_runtime.h>
#include <cuda_bf16.h>
#include <cstdint>

#define NH    16
#define NK    8
#define D_IN  1024
#define D_H   64
#define MT    256

// scratch (allocation-free rule: __device__ globals)
__device__ float         g_scores[8192 * NK];
__device__ __nv_bfloat16 g_bhi[NH * NK * 64 * 64];   // [h][c][o][i]  (B^T rows, 128B)
__device__ __nv_bfloat16 g_blo[NH * NK * 64 * 64];

__device__ __forceinline__ uint32_t smem_u32(const void* p) {
    uint32_t a;
    asm("{ .reg .u64 t; cvta.to.shared.u64 t, %1; cvt.u32.u64 %0, t; }" : "=r"(a) : "l"(p));
    return a;
}
__device__ __forceinline__ void ldmx4(uint32_t* r, uint32_t a) {
    asm volatile("ldmatrix.sync.aligned.m8n8.x4.shared.b16 {%0,%1,%2,%3}, [%4];"
                 : "=r"(r[0]), "=r"(r[1]), "=r"(r[2]), "=r"(r[3]) : "r"(a));
}
__device__ __forceinline__ void mma16816(float* d, const uint32_t* a, const uint32_t* b) {
    asm volatile("mma.sync.aligned.m16n8k16.row.col.f32.bf16.bf16.f32 "
                 "{%0,%1,%2,%3}, {%4,%5,%6,%7}, {%8,%9}, {%0,%1,%2,%3};"
                 : "+f"(d[0]), "+f"(d[1]), "+f"(d[2]), "+f"(d[3])
                 : "r"(a[0]), "r"(a[1]), "r"(a[2]), "r"(a[3]), "r"(b[0]), "r"(b[1]));
}

// ---------------------------------------------------------------------------
// Merged prep kernel.
//   blocks [0, 128):      wsplit — B^T hi/lo, 128B rows: g_b*[((h*8+c)*64+o)*64+i]
//   blocks [128, 128+M/8): scores[m,k] = phi[t,k] + sum_i x[m,i]*diag[k,i]
// ---------------------------------------------------------------------------
__global__ __launch_bounds__(256) void prep_kernel(
        const float* __restrict__ w,
        const float* __restrict__ x, const float* __restrict__ diag,
        const float* __restrict__ phi, int M, int T) {
    __shared__ float sbuf[NK * D_IN];          // 32 KB (wsplit uses first 16 KB)
    int tid = threadIdx.x;

    if (blockIdx.x < NH * NK) {
        // ---- wsplit path
        int hc = blockIdx.x;
        const float4* wg = (const float4*)(w + (size_t)hc * 4096);
        for (int idx = tid; idx < 1024; idx += 256)
            ((float4*)sbuf)[idx] = wg[idx];
        __syncthreads();

        int o = tid >> 2, q = tid & 3;
        __nv_bfloat16 hi[16], lo[16];
#pragma unroll
        for (int j = 0; j < 16; j++) {
            float v = sbuf[(q * 16 + j) * 64 + o];     // w[h][c][i][o]
            __nv_bfloat16 hb = __float2bfloat16_rn(v);
            hi[j] = hb;
            lo[j] = __float2bfloat16_rn(v - __bfloat162float(hb));
        }
        size_t base = ((size_t)hc * 64 + o) * 64 + q * 16;
        *(uint4*)(g_bhi + base)     = ((uint4*)hi)[0];
        *(uint4*)(g_bhi + base + 8) = ((uint4*)hi)[1];
        *(uint4*)(g_blo + base)     = ((uint4*)lo)[0];
        *(uint4*)(g_blo + base + 8) = ((uint4*)lo)[1];
        return;
    }

    // ---- scores path
    for (int idx = tid; idx < NK * D_IN / 4; idx += 256)
        ((float4*)sbuf)[idx] = ((const float4*)diag)[idx];
    __syncthreads();

    int warp = tid >> 5, lane = tid & 31;
    int m = (blockIdx.x - NH * NK) * 8 + warp;
    if (m >= M) return;

    const float4* xr = (const float4*)(x + (size_t)m * D_IN);
    float acc[NK];
#pragma unroll
    for (int k = 0; k < NK; k++) acc[k] = 0.f;
#pragma unroll
    for (int j = 0; j < 8; j++) {
        float4 xv = xr[j * 32 + lane];
#pragma unroll
        for (int k = 0; k < NK; k++) {
            float4 dv = *(const float4*)&sbuf[k * D_IN + j * 128 + lane * 4];
            acc[k] += xv.x * dv.x + xv.y * dv.y + xv.z * dv.z + xv.w * dv.w;
        }
    }
#pragma unroll
    for (int k = 0; k < NK; k++)
#pragma unroll
        for (int off = 16; off; off >>= 1)
            acc[k] += __shfl_xor_sync(0xffffffffu, acc[k], off);
    if (lane < NK) {
        float v = 0.f;
#pragma unroll
        for (int k = 0; k < NK; k++)
            if (lane == k) v = acc[k];
        int t = m % T;
        g_scores[m * NK + lane] = phi[t * NK + lane] + v;
    }
}

// ---------------------------------------------------------------------------
// Main: per (256-token tile, head). 256 threads, 8 warps; warp = m32 x n64.
//   P_c = X . B_c^T  (3-pass bf16 split, X frags register-resident)
//   acc += s[m,c] * (Pa + Pb)     Pa = hi*hi,  Pb = hi*lo + lo*hi
// Independent Pa/Pb accumulators double the HMMA dependency chains (latency fix).
// smem: Bhi 64K | Blo 64K | Xhi 32K | Xlo 32K | scores 8K = 200 KB.
// ---------------------------------------------------------------------------
#define SB_HI 0
#define SB_LO 65536
#define SX_HI 131072
#define SX_LO 163840
#define SS    196608
#define SMEM_TOTAL 204800

__global__ __launch_bounds__(256, 1) void main_kernel(
        const float* __restrict__ x, float* __restrict__ out) {
    extern __shared__ char sm[];
    int tid  = threadIdx.x;
    int lane = tid & 31, wid = tid >> 5;
    int h    = blockIdx.y;
    int m0   = blockIdx.x * MT;

    // --- B copy (linear read, swizzled store; 16B granules)
    {
        const uint4* gh = (const uint4*)(g_bhi + (size_t)h * NK * 64 * 64);
        const uint4* gl = (const uint4*)(g_blo + (size_t)h * NK * 64 * 64);
        for (int i = tid; i < 4096; i += 256) {
            uint32_t byte = i * 16;
            uint32_t dst  = (byte & ~127u) | ((byte & 127u) ^ (((byte >> 7) & 7u) << 4));
            *(uint4*)(sm + SB_HI + dst) = gh[i];
            *(uint4*)(sm + SB_LO + dst) = gl[i];
        }
    }
    // --- X split hi/lo (thread per row)
    {
        int r = tid;
        const float4* xp = (const float4*)(x + (size_t)(m0 + r) * D_IN + h * D_H);
        uint32_t rsw = (uint32_t)(r & 7) << 4;
#pragma unroll
        for (int j = 0; j < 8; j++) {
            float4 v0 = xp[2 * j], v1 = xp[2 * j + 1];
            float vv[8] = {v0.x, v0.y, v0.z, v0.w, v1.x, v1.y, v1.z, v1.w};
            __nv_bfloat16 hb[8], lb[8];
#pragma unroll
            for (int e = 0; e < 8; e++) {
                hb[e] = __float2bfloat16_rn(vv[e]);
                lb[e] = __float2bfloat16_rn(vv[e] - __bfloat162float(hb[e]));
            }
            uint32_t dst = r * 128 + ((uint32_t)(j * 16) ^ rsw);
            *(uint4*)(sm + SX_HI + dst) = *(uint4*)hb;
            *(uint4*)(sm + SX_LO + dst) = *(uint4*)lb;
        }
    }
    // --- scores tile
    {
        float* ssp = (float*)(sm + SS);
        const float* gs = g_scores + (size_t)m0 * NK;
        for (int i = tid; i < MT * NK; i += 256) ssp[i] = gs[i];
    }
    __syncthreads();

    // --- load X fragments (once)
    int a_r = lane & 15;
    uint32_t a_c = (uint32_t)((lane >> 4) * 16);
    uint32_t xbase = smem_u32(sm);
    uint32_t xh[2][4][4], xl[2][4][4];
#pragma unroll
    for (int mb = 0; mb < 2; mb++) {
        int row = wid * 32 + mb * 16 + a_r;
        uint32_t rsw = (uint32_t)(row & 7) << 4;
#pragma unroll
        for (int ks = 0; ks < 4; ks++) {
            uint32_t off = row * 128 + (((uint32_t)(ks * 32) + a_c) ^ rsw);
            ldmx4(xh[mb][ks], xbase + SX_HI + off);
            ldmx4(xl[mb][ks], xbase + SX_LO + off);
        }
    }

    // --- B lane address components
    int b_r = (lane & 7) + ((lane >> 4) & 1) * 8;
    uint32_t b_c = (uint32_t)(((lane >> 3) & 1) * 16);
    uint32_t brsw = (uint32_t)(b_r & 7) << 4;
    uint32_t bcol[4];
#pragma unroll
    for (int ks = 0; ks < 4; ks++)
        bcol[ks] = (((uint32_t)(ks * 32) + b_c) ^ brsw);

    float acc[2][4][2][4];
#pragma unroll
    for (int mb = 0; mb < 2; mb++)
#pragma unroll
        for (int p = 0; p < 4; p++)
#pragma unroll
            for (int nb = 0; nb < 2; nb++)
#pragma unroll
                for (int e = 0; e < 4; e++) acc[mb][p][nb][e] = 0.f;

    const float* ssp = (const float*)(sm + SS);
    int er0 = wid * 32 + (lane >> 2);          // epilogue row base (mb=0)

#pragma unroll 1
    for (int c = 0; c < NK; c++) {
        uint32_t bch = xbase + SB_HI + c * 8192;
        uint32_t bcl = xbase + SB_LO + c * 8192;
#pragma unroll 1
        for (int p = 0; p < 4; p++) {
            float Pa[2][2][4], Pb[2][2][4];
#pragma unroll
            for (int mb = 0; mb < 2; mb++)
#pragma unroll
                for (int nb = 0; nb < 2; nb++)
#pragma unroll
                    for (int e = 0; e < 4; e++) {
                        Pa[mb][nb][e] = 0.f;
                        Pb[mb][nb][e] = 0.f;
                    }

            uint32_t brow = (uint32_t)((p * 16 + b_r) * 128);
#pragma unroll
            for (int ks = 0; ks < 4; ks++) {
                uint32_t bh[4], bl[4];
                ldmx4(bh, bch + brow + bcol[ks]);
                ldmx4(bl, bcl + brow + bcol[ks]);
#pragma unroll
                for (int mb = 0; mb < 2; mb++)
#pragma unroll
                    for (int nb = 0; nb < 2; nb++) {
                        mma16816(Pa[mb][nb], xh[mb][ks], bh + 2 * nb);  // hi*hi
                        mma16816(Pb[mb][nb], xh[mb][ks], bl + 2 * nb);  // hi*lo
                        mma16816(Pb[mb][nb], xl[mb][ks], bh + 2 * nb);  // lo*hi
                    }
            }
            // epilogue: acc += s * (Pa + Pb)
#pragma unroll
            for (int mb = 0; mb < 2; mb++) {
                int r0 = er0 + mb * 16;
                float s0 = ssp[r0 * NK + c];
                float s1 = ssp[(r0 + 8) * NK + c];
#pragma unroll
                for (int nb = 0; nb < 2; nb++) {
                    acc[mb][p][nb][0] += s0 * (Pa[mb][nb][0] + Pb[mb][nb][0]);
                    acc[mb][p][nb][1] += s0 * (Pa[mb][nb][1] + Pb[mb][nb][1]);
                    acc[mb][p][nb][2] += s1 * (Pa[mb][nb][2] + Pb[mb][nb][2]);
                    acc[mb][p][nb][3] += s1 * (Pa[mb][nb][3] + Pb[mb][nb][3]);
                }
            }
        }
    }

    // --- store
#pragma unroll
    for (int mb = 0; mb < 2; mb++) {
        int m = m0 + wid * 32 + mb * 16 + (lane >> 2);
        float* o0 = out + (size_t)m * D_IN + h * D_H + (lane & 3) * 2;
#pragma unroll
        for (int p = 0; p < 4; p++)
#pragma unroll
            for (int nb = 0; nb < 2; nb++) {
                float2 v0 = make_float2(acc[mb][p][nb][0], acc[mb][p][nb][1]);
                float2 v1 = make_float2(acc[mb][p][nb][2], acc[mb][p][nb][3]);
                *(float2*)(o0 + p * 16 + nb * 8)                     = v0;
                *(float2*)(o0 + p * 16 + nb * 8 + 8 * (size_t)D_IN) = v1;
            }
    }
}

// ---------------------------------------------------------------------------
extern "C" void kernel_launch(void* const* d_in, const int* in_sizes, int n_in,
                              void* d_out, int out_size) {
    const float* x      = (const float*)d_in[0];
    const float* weight = (const float*)d_in[1];
    const float* diag   = (const float*)d_in[2];
    const float* phi    = (const float*)d_in[3];
    float* out          = (float*)d_out;

    int M = in_sizes[0] / D_IN;   // B*T tokens
    int T = in_sizes[3] / NK;     // phi rows

    cudaFuncSetAttribute(main_kernel,
                         cudaFuncAttributeMaxDynamicSharedMemorySize, SMEM_TOTAL);

    prep_kernel<<<NH * NK + (M + 7) / 8, 256>>>(weight, x, diag, phi, M, T);

    dim3 grid(M / MT, NH);
    main_kernel<<<grid, 256, SMEM_TOTAL>>>(x, out);
}

// round 8
// speedup vs baseline: 1.0379x; 1.0379x over previous
#include <cuda_runtime.h>
#include <cuda_bf16.h>
#include <cstdint>

#define NH    16
#define NK    8
#define D_IN  1024
#define D_H   64
#define MT    256

// scratch (allocation-free rule: __device__ globals)
__device__ float         g_scores[8192 * NK];
__device__ __nv_bfloat16 g_bhi[NH * NK * 64 * 64];   // [h][c][o][i]  (B^T rows, 128B)
__device__ __nv_bfloat16 g_blo[NH * NK * 64 * 64];

__device__ __forceinline__ uint32_t smem_u32(const void* p) {
    uint32_t a;
    asm("{ .reg .u64 t; cvta.to.shared.u64 t, %1; cvt.u32.u64 %0, t; }" : "=r"(a) : "l"(p));
    return a;
}
__device__ __forceinline__ void ldmx4(uint32_t* r, uint32_t a) {
    asm volatile("ldmatrix.sync.aligned.m8n8.x4.shared.b16 {%0,%1,%2,%3}, [%4];"
                 : "=r"(r[0]), "=r"(r[1]), "=r"(r[2]), "=r"(r[3]) : "r"(a));
}
__device__ __forceinline__ void mma16816(float* d, const uint32_t* a, const uint32_t* b) {
    asm volatile("mma.sync.aligned.m16n8k16.row.col.f32.bf16.bf16.f32 "
                 "{%0,%1,%2,%3}, {%4,%5,%6,%7}, {%8,%9}, {%0,%1,%2,%3};"
                 : "+f"(d[0]), "+f"(d[1]), "+f"(d[2]), "+f"(d[3])
                 : "r"(a[0]), "r"(a[1]), "r"(a[2]), "r"(a[3]), "r"(b[0]), "r"(b[1]));
}

// ---------------------------------------------------------------------------
// Merged prep kernel.
//   blocks [0, 128):       wsplit — B^T hi/lo, 128B rows: g_b*[((h*8+c)*64+o)*64+i]
//   blocks [128, 128+M/8): scores[m,k] = phi[t,k] + sum_i x[m,i]*diag[k,i]
// ---------------------------------------------------------------------------
__global__ __launch_bounds__(256) void prep_kernel(
        const float* __restrict__ w,
        const float* __restrict__ x, const float* __restrict__ diag,
        const float* __restrict__ phi, int M, int T) {
    __shared__ float sbuf[NK * D_IN];
    int tid = threadIdx.x;

    if (blockIdx.x < NH * NK) {
        int hc = blockIdx.x;
        const float4* wg = (const float4*)(w + (size_t)hc * 4096);
        for (int idx = tid; idx < 1024; idx += 256)
            ((float4*)sbuf)[idx] = wg[idx];
        __syncthreads();

        int o = tid >> 2, q = tid & 3;
        __nv_bfloat16 hi[16], lo[16];
#pragma unroll
        for (int j = 0; j < 16; j++) {
            float v = sbuf[(q * 16 + j) * 64 + o];
            __nv_bfloat16 hb = __float2bfloat16_rn(v);
            hi[j] = hb;
            lo[j] = __float2bfloat16_rn(v - __bfloat162float(hb));
        }
        size_t base = ((size_t)hc * 64 + o) * 64 + q * 16;
        *(uint4*)(g_bhi + base)     = ((uint4*)hi)[0];
        *(uint4*)(g_bhi + base + 8) = ((uint4*)hi)[1];
        *(uint4*)(g_blo + base)     = ((uint4*)lo)[0];
        *(uint4*)(g_blo + base + 8) = ((uint4*)lo)[1];
        return;
    }

    for (int idx = tid; idx < NK * D_IN / 4; idx += 256)
        ((float4*)sbuf)[idx] = ((const float4*)diag)[idx];
    __syncthreads();

    int warp = tid >> 5, lane = tid & 31;
    int m = (blockIdx.x - NH * NK) * 8 + warp;
    if (m >= M) return;

    const float4* xr = (const float4*)(x + (size_t)m * D_IN);
    float acc[NK];
#pragma unroll
    for (int k = 0; k < NK; k++) acc[k] = 0.f;
#pragma unroll
    for (int j = 0; j < 8; j++) {
        float4 xv = xr[j * 32 + lane];
#pragma unroll
        for (int k = 0; k < NK; k++) {
            float4 dv = *(const float4*)&sbuf[k * D_IN + j * 128 + lane * 4];
            acc[k] += xv.x * dv.x + xv.y * dv.y + xv.z * dv.z + xv.w * dv.w;
        }
    }
#pragma unroll
    for (int k = 0; k < NK; k++)
#pragma unroll
        for (int off = 16; off; off >>= 1)
            acc[k] += __shfl_xor_sync(0xffffffffu, acc[k], off);
    if (lane < NK) {
        float v = 0.f;
#pragma unroll
        for (int k = 0; k < NK; k++)
            if (lane == k) v = acc[k];
        int t = m % T;
        g_scores[m * NK + lane] = phi[t * NK + lane] + v;
    }
}

// ---------------------------------------------------------------------------
// Main: per (256-token tile, head). 512 threads, 16 warps; warp = m16 x n64.
//   P_c = X . B_c^T  (3-pass bf16 split; Pa/Pb/Pc independent chains of 4)
//   acc += s[m,c] * (Pa + Pb + Pc)
// smem: Bhi 64K | Blo 64K | Xhi 32K | Xlo 32K | scores 8K = 200 KB.
// ---------------------------------------------------------------------------
#define SB_HI 0
#define SB_LO 65536
#define SX_HI 131072
#define SX_LO 163840
#define SS    196608
#define SMEM_TOTAL 204800

__global__ __launch_bounds__(512, 1) void main_kernel(
        const float* __restrict__ x, float* __restrict__ out) {
    extern __shared__ char sm[];
    int tid  = threadIdx.x;
    int lane = tid & 31, wid = tid >> 5;     // wid 0..15
    int h    = blockIdx.y;
    int m0   = blockIdx.x * MT;

    // --- B copy (linear read, swizzled store; 16B granules)
    {
        const uint4* gh = (const uint4*)(g_bhi + (size_t)h * NK * 64 * 64);
        const uint4* gl = (const uint4*)(g_blo + (size_t)h * NK * 64 * 64);
        for (int i = tid; i < 4096; i += 512) {
            uint32_t byte = i * 16;
            uint32_t dst  = (byte & ~127u) | ((byte & 127u) ^ (((byte >> 7) & 7u) << 4));
            *(uint4*)(sm + SB_HI + dst) = gh[i];
            *(uint4*)(sm + SB_LO + dst) = gl[i];
        }
    }
    // --- X split hi/lo (2 threads per row, 4 float4 groups each)
    {
        int r = tid >> 1, j0 = (tid & 1) * 4;
        const float4* xp = (const float4*)(x + (size_t)(m0 + r) * D_IN + h * D_H);
        uint32_t rsw = (uint32_t)(r & 7) << 4;
#pragma unroll
        for (int jj = 0; jj < 4; jj++) {
            int j = j0 + jj;
            float4 v0 = xp[2 * j], v1 = xp[2 * j + 1];
            float vv[8] = {v0.x, v0.y, v0.z, v0.w, v1.x, v1.y, v1.z, v1.w};
            __nv_bfloat16 hb[8], lb[8];
#pragma unroll
            for (int e = 0; e < 8; e++) {
                hb[e] = __float2bfloat16_rn(vv[e]);
                lb[e] = __float2bfloat16_rn(vv[e] - __bfloat162float(hb[e]));
            }
            uint32_t dst = r * 128 + ((uint32_t)(j * 16) ^ rsw);
            *(uint4*)(sm + SX_HI + dst) = *(uint4*)hb;
            *(uint4*)(sm + SX_LO + dst) = *(uint4*)lb;
        }
    }
    // --- scores tile
    {
        float* ssp = (float*)(sm + SS);
        const float* gs = g_scores + (size_t)m0 * NK;
        for (int i = tid; i < MT * NK; i += 512) ssp[i] = gs[i];
    }
    __syncthreads();

    // --- load X fragments once (m16 per warp)
    int a_r = lane & 15;
    uint32_t a_c = (uint32_t)((lane >> 4) * 16);
    uint32_t xbase = smem_u32(sm);
    uint32_t xh[4][4], xl[4][4];
    {
        int row = wid * 16 + a_r;
        uint32_t rsw = (uint32_t)(row & 7) << 4;
#pragma unroll
        for (int ks = 0; ks < 4; ks++) {
            uint32_t off = row * 128 + (((uint32_t)(ks * 32) + a_c) ^ rsw);
            ldmx4(xh[ks], xbase + SX_HI + off);
            ldmx4(xl[ks], xbase + SX_LO + off);
        }
    }

    // --- B lane address components
    int b_r = (lane & 7) + ((lane >> 4) & 1) * 8;
    uint32_t b_c = (uint32_t)(((lane >> 3) & 1) * 16);
    uint32_t brsw = (uint32_t)(b_r & 7) << 4;
    uint32_t bcol[4];
#pragma unroll
    for (int ks = 0; ks < 4; ks++)
        bcol[ks] = (((uint32_t)(ks * 32) + b_c) ^ brsw);

    float acc[4][2][4];
#pragma unroll
    for (int p = 0; p < 4; p++)
#pragma unroll
        for (int nb = 0; nb < 2; nb++)
#pragma unroll
            for (int e = 0; e < 4; e++) acc[p][nb][e] = 0.f;

    const float* ssp = (const float*)(sm + SS);
    int er0 = wid * 16 + (lane >> 2);

#pragma unroll 1
    for (int c = 0; c < NK; c++) {
        uint32_t bch = xbase + SB_HI + c * 8192;
        uint32_t bcl = xbase + SB_LO + c * 8192;
        float s0 = ssp[er0 * NK + c];
        float s1 = ssp[(er0 + 8) * NK + c];
#pragma unroll 1
        for (int p = 0; p < 4; p++) {
            float Pa[2][4], Pb[2][4], Pc[2][4];
#pragma unroll
            for (int nb = 0; nb < 2; nb++)
#pragma unroll
                for (int e = 0; e < 4; e++) {
                    Pa[nb][e] = 0.f; Pb[nb][e] = 0.f; Pc[nb][e] = 0.f;
                }

            uint32_t brow = (uint32_t)((p * 16 + b_r) * 128);
#pragma unroll
            for (int ks = 0; ks < 4; ks++) {
                uint32_t bh[4], bl[4];
                ldmx4(bh, bch + brow + bcol[ks]);
                ldmx4(bl, bcl + brow + bcol[ks]);
#pragma unroll
                for (int nb = 0; nb < 2; nb++) {
                    mma16816(Pa[nb], xh[ks], bh + 2 * nb);  // hi*hi
                    mma16816(Pb[nb], xh[ks], bl + 2 * nb);  // hi*lo
                    mma16816(Pc[nb], xl[ks], bh + 2 * nb);  // lo*hi
                }
            }
#pragma unroll
            for (int nb = 0; nb < 2; nb++) {
                acc[p][nb][0] += s0 * (Pa[nb][0] + Pb[nb][0] + Pc[nb][0]);
                acc[p][nb][1] += s0 * (Pa[nb][1] + Pb[nb][1] + Pc[nb][1]);
                acc[p][nb][2] += s1 * (Pa[nb][2] + Pb[nb][2] + Pc[nb][2]);
                acc[p][nb][3] += s1 * (Pa[nb][3] + Pb[nb][3] + Pc[nb][3]);
            }
        }
    }

    // --- store: warp rows [wid*16, wid*16+16)
    {
        int m = m0 + wid * 16 + (lane >> 2);
        float* o0 = out + (size_t)m * D_IN + h * D_H + (lane & 3) * 2;
#pragma unroll
        for (int p = 0; p < 4; p++)
#pragma unroll
            for (int nb = 0; nb < 2; nb++) {
                float2 v0 = make_float2(acc[p][nb][0], acc[p][nb][1]);
                float2 v1 = make_float2(acc[p][nb][2], acc[p][nb][3]);
                *(float2*)(o0 + p * 16 + nb * 8)                     = v0;
                *(float2*)(o0 + p * 16 + nb * 8 + 8 * (size_t)D_IN) = v1;
            }
    }
}

// ---------------------------------------------------------------------------
extern "C" void kernel_launch(void* const* d_in, const int* in_sizes, int n_in,
                              void* d_out, int out_size) {
    const float* x      = (const float*)d_in[0];
    const float* weight = (const float*)d_in[1];
    const float* diag   = (const float*)d_in[2];
    const float* phi    = (const float*)d_in[3];
    float* out          = (float*)d_out;

    int M = in_sizes[0] / D_IN;   // B*T tokens
    int T = in_sizes[3] / NK;     // phi rows

    cudaFuncSetAttribute(main_kernel,
                         cudaFuncAttributeMaxDynamicSharedMemorySize, SMEM_TOTAL);

    prep_kernel<<<NH * NK + (M + 7) / 8, 256>>>(weight, x, diag, phi, M, T);

    dim3 grid(M / MT, NH);
    main_kernel<<<grid, 512, SMEM_TOTAL>>>(x, out);
}

// round 9
// speedup vs baseline: 1.0480x; 1.0098x over previous
#include <cuda_runtime.h>
#include <cuda_bf16.h>
#include <cstdint>

#define NH    16
#define NK    8
#define D_IN  1024
#define D_H   64
#define MT    256

// scratch (allocation-free rule: __device__ globals)
__device__ float         g_scores[8192 * NK];
__device__ __nv_bfloat16 g_bhi[NH * NK * 64 * 64];   // [h][c][o][i]  (B^T rows, 128B)
__device__ __nv_bfloat16 g_blo[NH * NK * 64 * 64];

__device__ __forceinline__ uint32_t smem_u32(const void* p) {
    uint32_t a;
    asm("{ .reg .u64 t; cvta.to.shared.u64 t, %1; cvt.u32.u64 %0, t; }" : "=r"(a) : "l"(p));
    return a;
}
__device__ __forceinline__ void ldmx4(uint32_t* r, uint32_t a) {
    asm volatile("ldmatrix.sync.aligned.m8n8.x4.shared.b16 {%0,%1,%2,%3}, [%4];"
                 : "=r"(r[0]), "=r"(r[1]), "=r"(r[2]), "=r"(r[3]) : "r"(a));
}
__device__ __forceinline__ void mma16816(float* d, const uint32_t* a, const uint32_t* b) {
    asm volatile("mma.sync.aligned.m16n8k16.row.col.f32.bf16.bf16.f32 "
                 "{%0,%1,%2,%3}, {%4,%5,%6,%7}, {%8,%9}, {%0,%1,%2,%3};"
                 : "+f"(d[0]), "+f"(d[1]), "+f"(d[2]), "+f"(d[3])
                 : "r"(a[0]), "r"(a[1]), "r"(a[2]), "r"(a[3]), "r"(b[0]), "r"(b[1]));
}

// ---------------------------------------------------------------------------
// Merged prep kernel.
//   blocks [0, 128):       wsplit — B^T hi/lo, 128B rows: g_b*[((h*8+c)*64+o)*64+i]
//   blocks [128, 128+M/8): scores[m,k] = phi[t,k] + sum_i x[m,i]*diag[k,i]
// ---------------------------------------------------------------------------
__global__ __launch_bounds__(256) void prep_kernel(
        const float* __restrict__ w,
        const float* __restrict__ x, const float* __restrict__ diag,
        const float* __restrict__ phi, int M, int T) {
    __shared__ float sbuf[NK * D_IN];
    int tid = threadIdx.x;

    if (blockIdx.x < NH * NK) {
        int hc = blockIdx.x;
        const float4* wg = (const float4*)(w + (size_t)hc * 4096);
        for (int idx = tid; idx < 1024; idx += 256)
            ((float4*)sbuf)[idx] = wg[idx];
        __syncthreads();

        int o = tid >> 2, q = tid & 3;
        __nv_bfloat16 hi[16], lo[16];
#pragma unroll
        for (int j = 0; j < 16; j++) {
            float v = sbuf[(q * 16 + j) * 64 + o];
            __nv_bfloat16 hb = __float2bfloat16_rn(v);
            hi[j] = hb;
            lo[j] = __float2bfloat16_rn(v - __bfloat162float(hb));
        }
        size_t base = ((size_t)hc * 64 + o) * 64 + q * 16;
        *(uint4*)(g_bhi + base)     = ((uint4*)hi)[0];
        *(uint4*)(g_bhi + base + 8) = ((uint4*)hi)[1];
        *(uint4*)(g_blo + base)     = ((uint4*)lo)[0];
        *(uint4*)(g_blo + base + 8) = ((uint4*)lo)[1];
        return;
    }

    for (int idx = tid; idx < NK * D_IN / 4; idx += 256)
        ((float4*)sbuf)[idx] = ((const float4*)diag)[idx];
    __syncthreads();

    int warp = tid >> 5, lane = tid & 31;
    int m = (blockIdx.x - NH * NK) * 8 + warp;
    if (m >= M) return;

    const float4* xr = (const float4*)(x + (size_t)m * D_IN);
    float acc[NK];
#pragma unroll
    for (int k = 0; k < NK; k++) acc[k] = 0.f;
#pragma unroll
    for (int j = 0; j < 8; j++) {
        float4 xv = xr[j * 32 + lane];
#pragma unroll
        for (int k = 0; k < NK; k++) {
            float4 dv = *(const float4*)&sbuf[k * D_IN + j * 128 + lane * 4];
            acc[k] += xv.x * dv.x + xv.y * dv.y + xv.z * dv.z + xv.w * dv.w;
        }
    }
#pragma unroll
    for (int k = 0; k < NK; k++)
#pragma unroll
        for (int off = 16; off; off >>= 1)
            acc[k] += __shfl_xor_sync(0xffffffffu, acc[k], off);
    if (lane < NK) {
        float v = 0.f;
#pragma unroll
        for (int k = 0; k < NK; k++)
            if (lane == k) v = acc[k];
        int t = m % T;
        g_scores[m * NK + lane] = phi[t * NK + lane] + v;
    }
}

// ---------------------------------------------------------------------------
// Main: per (256-token tile, head). 512 threads, 16 warps; warp = m16 x n64.
//   P_c = X . B_c^T  (3-pass bf16 split; Pa/Pb/Pc independent chains of 4)
//   acc += s[m,c] * (Pa + Pb + Pc)
// smem: Bhi 64K | Blo 64K | Xhi 32K | Xlo 32K | scores 8K = 200 KB.
// ---------------------------------------------------------------------------
#define SB_HI 0
#define SB_LO 65536
#define SX_HI 131072
#define SX_LO 163840
#define SS    196608
#define SMEM_TOTAL 204800

__global__ __launch_bounds__(512, 1) void main_kernel(
        const float* __restrict__ x, float* __restrict__ out) {
    extern __shared__ char sm[];
    int tid  = threadIdx.x;
    int lane = tid & 31, wid = tid >> 5;     // wid 0..15
    int h    = blockIdx.y;
    int m0   = blockIdx.x * MT;

    // --- B copy (linear read, swizzled store; 16B granules)
    {
        const uint4* gh = (const uint4*)(g_bhi + (size_t)h * NK * 64 * 64);
        const uint4* gl = (const uint4*)(g_blo + (size_t)h * NK * 64 * 64);
        for (int i = tid; i < 4096; i += 512) {
            uint32_t byte = i * 16;
            uint32_t dst  = (byte & ~127u) | ((byte & 127u) ^ (((byte >> 7) & 7u) << 4));
            *(uint4*)(sm + SB_HI + dst) = gh[i];
            *(uint4*)(sm + SB_LO + dst) = gl[i];
        }
    }
    // --- X split hi/lo (2 threads per row, 4 float4 groups each)
    {
        int r = tid >> 1, j0 = (tid & 1) * 4;
        const float4* xp = (const float4*)(x + (size_t)(m0 + r) * D_IN + h * D_H);
        uint32_t rsw = (uint32_t)(r & 7) << 4;
#pragma unroll
        for (int jj = 0; jj < 4; jj++) {
            int j = j0 + jj;
            float4 v0 = xp[2 * j], v1 = xp[2 * j + 1];
            float vv[8] = {v0.x, v0.y, v0.z, v0.w, v1.x, v1.y, v1.z, v1.w};
            __nv_bfloat16 hb[8], lb[8];
#pragma unroll
            for (int e = 0; e < 8; e++) {
                hb[e] = __float2bfloat16_rn(vv[e]);
                lb[e] = __float2bfloat16_rn(vv[e] - __bfloat162float(hb[e]));
            }
            uint32_t dst = r * 128 + ((uint32_t)(j * 16) ^ rsw);
            *(uint4*)(sm + SX_HI + dst) = *(uint4*)hb;
            *(uint4*)(sm + SX_LO + dst) = *(uint4*)lb;
        }
    }
    // --- scores tile
    {
        float* ssp = (float*)(sm + SS);
        const float* gs = g_scores + (size_t)m0 * NK;
        for (int i = tid; i < MT * NK; i += 512) ssp[i] = gs[i];
    }
    __syncthreads();

    // --- load X fragments once (m16 per warp)
    int a_r = lane & 15;
    uint32_t a_c = (uint32_t)((lane >> 4) * 16);
    uint32_t xbase = smem_u32(sm);
    uint32_t xh[4][4], xl[4][4];
    {
        int row = wid * 16 + a_r;
        uint32_t rsw = (uint32_t)(row & 7) << 4;
#pragma unroll
        for (int ks = 0; ks < 4; ks++) {
            uint32_t off = row * 128 + (((uint32_t)(ks * 32) + a_c) ^ rsw);
            ldmx4(xh[ks], xbase + SX_HI + off);
            ldmx4(xl[ks], xbase + SX_LO + off);
        }
    }

    // --- B lane address components
    int b_r = (lane & 7) + ((lane >> 4) & 1) * 8;
    uint32_t b_c = (uint32_t)(((lane >> 3) & 1) * 16);
    uint32_t brsw = (uint32_t)(b_r & 7) << 4;
    uint32_t bcol[4];
#pragma unroll
    for (int ks = 0; ks < 4; ks++)
        bcol[ks] = (((uint32_t)(ks * 32) + b_c) ^ brsw);

    float acc[4][2][4];
#pragma unroll
    for (int p = 0; p < 4; p++)
#pragma unroll
        for (int nb = 0; nb < 2; nb++)
#pragma unroll
            for (int e = 0; e < 4; e++) acc[p][nb][e] = 0.f;

    const float* ssp = (const float*)(sm + SS);
    int er0 = wid * 16 + (lane >> 2);

#pragma unroll 1
    for (int c = 0; c < NK; c++) {
        uint32_t bch = xbase + SB_HI + c * 8192;
        uint32_t bcl = xbase + SB_LO + c * 8192;
        float s0 = ssp[er0 * NK + c];
        float s1 = ssp[(er0 + 8) * NK + c];
#pragma unroll 1
        for (int p = 0; p < 4; p++) {
            float Pa[2][4], Pb[2][4], Pc[2][4];
#pragma unroll
            for (int nb = 0; nb < 2; nb++)
#pragma unroll
                for (int e = 0; e < 4; e++) {
                    Pa[nb][e] = 0.f; Pb[nb][e] = 0.f; Pc[nb][e] = 0.f;
                }

            uint32_t brow = (uint32_t)((p * 16 + b_r) * 128);
#pragma unroll
            for (int ks = 0; ks < 4; ks++) {
                uint32_t bh[4], bl[4];
                ldmx4(bh, bch + brow + bcol[ks]);
                ldmx4(bl, bcl + brow + bcol[ks]);
#pragma unroll
                for (int nb = 0; nb < 2; nb++) {
                    mma16816(Pa[nb], xh[ks], bh + 2 * nb);  // hi*hi
                    mma16816(Pb[nb], xh[ks], bl + 2 * nb);  // hi*lo
                    mma16816(Pc[nb], xl[ks], bh + 2 * nb);  // lo*hi
                }
            }
#pragma unroll
            for (int nb = 0; nb < 2; nb++) {
                acc[p][nb][0] += s0 * (Pa[nb][0] + Pb[nb][0] + Pc[nb][0]);
                acc[p][nb][1] += s0 * (Pa[nb][1] + Pb[nb][1] + Pc[nb][1]);
                acc[p][nb][2] += s1 * (Pa[nb][2] + Pb[nb][2] + Pc[nb][2]);
                acc[p][nb][3] += s1 * (Pa[nb][3] + Pb[nb][3] + Pc[nb][3]);
            }
        }
    }

    // --- store: warp rows [wid*16, wid*16+16)
    {
        int m = m0 + wid * 16 + (lane >> 2);
        float* o0 = out + (size_t)m * D_IN + h * D_H + (lane & 3) * 2;
#pragma unroll
        for (int p = 0; p < 4; p++)
#pragma unroll
            for (int nb = 0; nb < 2; nb++) {
                float2 v0 = make_float2(acc[p][nb][0], acc[p][nb][1]);
                float2 v1 = make_float2(acc[p][nb][2], acc[p][nb][3]);
                *(float2*)(o0 + p * 16 + nb * 8)                     = v0;
                *(float2*)(o0 + p * 16 + nb * 8 + 8 * (size_t)D_IN) = v1;
            }
    }
}

// ---------------------------------------------------------------------------
extern "C" void kernel_launch(void* const* d_in, const int* in_sizes, int n_in,
                              void* d_out, int out_size) {
    const float* x      = (const float*)d_in[0];
    const float* weight = (const float*)d_in[1];
    const float* diag   = (const float*)d_in[2];
    const float* phi    = (const float*)d_in[3];
    float* out          = (float*)d_out;

    int M = in_sizes[0] / D_IN;   // B*T tokens
    int T = in_sizes[3] / NK;     // phi rows

    cudaFuncSetAttribute(main_kernel,
                         cudaFuncAttributeMaxDynamicSharedMemorySize, SMEM_TOTAL);

    prep_kernel<<<NH * NK + (M + 7) / 8, 256>>>(weight, x, diag, phi, M, T);

    dim3 grid(M / MT, NH);
    main_kernel<<<grid, 512, SMEM_TOTAL>>>(x, out);
}